// round 13
// baseline (speedup 1.0000x reference)
#include <cuda_runtime.h>

#define BB 256
#define TT 512
#define EMBD 64
#define HID 128

__device__ float g_pre1[(long)TT * BB * HID];   // [t][b][j], 64 MB

// tanh(x) = 1 - 2/(e^{2x}+1) via MUFU. |err| ~1e-7 per call.
__device__ __forceinline__ float fast_tanh(float x) {
    float xc = fminf(fmaxf(x, -20.f), 20.f);
    float e;
    asm("ex2.approx.f32 %0, %1;" : "=f"(e) : "f"(xc * 2.8853900817779268f));
    float r;
    asm("rcp.approx.f32 %0, %1;" : "=f"(r) : "f"(e + 1.f));
    return fmaf(-2.f, r, 1.f);
}

// ---------------------------------------------------------------------------
// Kernel 1: pre1[t][b][j] = dot(emb[x[b,t]], Wih1[j]) + b_ih1[j] + b_hh1[j]
// (proven R1 version, byte-identical)
// ---------------------------------------------------------------------------
__global__ __launch_bounds__(128) void k_pre1(
    const int* __restrict__ x, const float* __restrict__ emb,
    const float* __restrict__ Wih1, const float* __restrict__ bih1,
    const float* __restrict__ bhh1)
{
    __shared__ __align__(16) float shW[HID * 68];
    __shared__ __align__(16) float4 shE[8 * 16];
    __shared__ int shX[8];

    const int tid = threadIdx.x;

    for (int it = 0; it < 64; ++it) {
        int f = it * 128 + tid;
        int j = f >> 6, k = f & 63;
        shW[j * 68 + k] = Wih1[f];
    }
    __syncthreads();

    float Wr[64];
#pragma unroll
    for (int i = 0; i < 64; ++i) Wr[i] = shW[tid * 68 + i];
    const float bb = bih1[tid] + bhh1[tid];

    const int base = blockIdx.x * 256;
    const float4* __restrict__ e4 = (const float4*)emb;

    for (int it = 0; it < 32; ++it) {
        const int rid0 = base + it * 8;             // rid = t*256 + b
        if (tid < 8) {
            int rid = rid0 + tid;
            int t = rid >> 8, b = rid & 255;
            shX[tid] = x[b * TT + t];
        }
        __syncthreads();
        {
            int r = tid >> 4, f = tid & 15;
            shE[r * 16 + f] = e4[(long)shX[r] * 16 + f];
        }
        __syncthreads();

        float acc[8];
#pragma unroll
        for (int r = 0; r < 8; ++r) acc[r] = bb;
#pragma unroll
        for (int k4 = 0; k4 < 16; ++k4) {
#pragma unroll
            for (int r = 0; r < 8; ++r) {
                float4 e = shE[r * 16 + k4];
                acc[r] = fmaf(Wr[4 * k4 + 0], e.x, acc[r]);
                acc[r] = fmaf(Wr[4 * k4 + 1], e.y, acc[r]);
                acc[r] = fmaf(Wr[4 * k4 + 2], e.z, acc[r]);
                acc[r] = fmaf(Wr[4 * k4 + 3], e.w, acc[r]);
            }
        }
#pragma unroll
        for (int r = 0; r < 8; ++r)
            g_pre1[(long)(rid0 + r) * HID + tid] = acc[r];
        __syncthreads();
    }
}

// ---------------------------------------------------------------------------
// Kernel 2: fused two-layer scan with PIPELINED LAYER 2 + fused epilogue.
// Iteration t computes h1_t AND h2_{t-1}; all three matvecs read only
// previous-iteration state => ONE compute phase + ONE combine phase,
// 2 barriers/step. Extra half-iteration (t == TT) finishes h2_{TT-1}.
// 128 CTAs x 256 threads; CTA handles rows b0, b0+1.
// Thread (j = tid&127, p = tid>>7) holds k-half rows of W_hh1/W_ih2/W_hh2.
// ---------------------------------------------------------------------------
__global__ __launch_bounds__(256, 1) void k_scan(
    const float* __restrict__ Whh1, const float* __restrict__ Wih2,
    const float* __restrict__ Whh2, const float* __restrict__ bih2,
    const float* __restrict__ bhh2,
    const float* __restrict__ ln_g, const float* __restrict__ ln_b,
    const float* __restrict__ projW, const float* __restrict__ proj_b,
    const float* __restrict__ on_g, const float* __restrict__ on_b,
    float* __restrict__ out)
{
    __shared__ __align__(16) float h1s[2][2][HID];   // [buf][row][j]  h1_{t-1}
    __shared__ __align__(16) float h2s[2][2][HID];   // [buf][row][j]  h2_{t-2}
    __shared__ __align__(16) float pA[2][2][HID];    // Whh1 partials [half][row][j]
    __shared__ __align__(16) float pB[2][2][HID];    // Wih2+Whh2 partials
    __shared__ __align__(16) float rep[2][HID];
    __shared__ float red[2][8];

    const int tid = threadIdx.x;
    const int j = tid & 127;
    const int p = tid >> 7;            // k-half (warp-uniform)
    const int b0 = blockIdx.x * 2;

    float W1r[64], Wi2r[64], W2r[64];
    {
        const float* w1 = Whh1 + j * HID + p * 64;
        const float* wi = Wih2 + j * HID + p * 64;
        const float* w2 = Whh2 + j * HID + p * 64;
#pragma unroll
        for (int i = 0; i < 64; ++i) { W1r[i] = w1[i]; Wi2r[i] = wi[i]; W2r[i] = w2[i]; }
    }
    const float bb2 = bih2[j] + bhh2[j];

    // Zero both buffers of both states.
    h1s[0][p][j] = 0.f; h1s[1][p][j] = 0.f;
    h2s[0][p][j] = 0.f; h2s[1][p][j] = 0.f;
    __syncthreads();

    const float* preBase = g_pre1 + (long)(b0 + p) * HID + j;
    float pre_r = preBase[0];

    const float4* h1b0[2] = { (const float4*)&h1s[0][0][p * 64], (const float4*)&h1s[1][0][p * 64] };
    const float4* h1b1[2] = { (const float4*)&h1s[0][1][p * 64], (const float4*)&h1s[1][1][p * 64] };
    const float4* h2b0[2] = { (const float4*)&h2s[0][0][p * 64], (const float4*)&h2s[1][0][p * 64] };
    const float4* h2b1[2] = { (const float4*)&h2s[0][1][p * 64], (const float4*)&h2s[1][1][p * 64] };

    for (int t = 0; t <= TT; ++t) {
        const int cur = t & 1, nxt = cur ^ 1;

        // ---- Compute phase: all three matvecs on old state ----
        // a: Whh1 . h1_{t-1};  f: Wih2 . h1_{t-1} + Whh2 . h2_{t-2}
        const float4* u0 = h1b0[cur];
        const float4* u1 = h1b1[cur];
        const float4* v0 = h2b0[cur];
        const float4* v1 = h2b1[cur];
        float a0 = 0.f, a1 = 0.f, f0 = 0.f, f1 = 0.f;
#pragma unroll
        for (int i = 0; i < 16; ++i) {
            float4 h0 = u0[i];                      // h1_{t-1} row 0 (shared by a & c)
            a0 = fmaf(W1r[4 * i + 0], h0.x, a0);
            a0 = fmaf(W1r[4 * i + 1], h0.y, a0);
            a0 = fmaf(W1r[4 * i + 2], h0.z, a0);
            a0 = fmaf(W1r[4 * i + 3], h0.w, a0);
            f0 = fmaf(Wi2r[4 * i + 0], h0.x, f0);
            f0 = fmaf(Wi2r[4 * i + 1], h0.y, f0);
            f0 = fmaf(Wi2r[4 * i + 2], h0.z, f0);
            f0 = fmaf(Wi2r[4 * i + 3], h0.w, f0);
            float4 h1 = u1[i];                      // h1_{t-1} row 1
            a1 = fmaf(W1r[4 * i + 0], h1.x, a1);
            a1 = fmaf(W1r[4 * i + 1], h1.y, a1);
            a1 = fmaf(W1r[4 * i + 2], h1.z, a1);
            a1 = fmaf(W1r[4 * i + 3], h1.w, a1);
            f1 = fmaf(Wi2r[4 * i + 0], h1.x, f1);
            f1 = fmaf(Wi2r[4 * i + 1], h1.y, f1);
            f1 = fmaf(Wi2r[4 * i + 2], h1.z, f1);
            f1 = fmaf(Wi2r[4 * i + 3], h1.w, f1);
            float4 g0 = v0[i];                      // h2_{t-2} row 0
            f0 = fmaf(W2r[4 * i + 0], g0.x, f0);
            f0 = fmaf(W2r[4 * i + 1], g0.y, f0);
            f0 = fmaf(W2r[4 * i + 2], g0.z, f0);
            f0 = fmaf(W2r[4 * i + 3], g0.w, f0);
            float4 g1 = v1[i];                      // h2_{t-2} row 1
            f1 = fmaf(W2r[4 * i + 0], g1.x, f1);
            f1 = fmaf(W2r[4 * i + 1], g1.y, f1);
            f1 = fmaf(W2r[4 * i + 2], g1.z, f1);
            f1 = fmaf(W2r[4 * i + 3], g1.w, f1);
        }
        pA[p][0][j] = a0;
        pA[p][1][j] = a1;
        pB[p][0][j] = f0;
        pB[p][1][j] = f1;
        __syncthreads();

        // ---- Combine phase: thread (j,p) finishes row p ----
        if (t < TT) {
            float v = pre_r + pA[0][p][j] + pA[1][p][j];
            h1s[nxt][p][j] = fast_tanh(v);
            if (t + 1 < TT) pre_r = preBase[(long)(t + 1) * BB * HID];
        }
        {
            float h2v = (t == 0) ? 0.f
                        : fast_tanh(bb2 + pB[0][p][j] + pB[1][p][j]);
            h2s[nxt][p][j] = h2v;
        }
        __syncthreads();
    }

    // h2_{TT-1} lives in h2s[(TT & 1) ^ 1] = h2s[1].
    // ---- Fused epilogue: LN -> proj -> tanh -> LN for row p ----
    const int wg = (tid >> 5) & 3;
    float v = h2s[1][p][j];

    float s = v, q = v * v;
#pragma unroll
    for (int o = 16; o; o >>= 1) {
        s += __shfl_xor_sync(0xffffffffu, s, o);
        q += __shfl_xor_sync(0xffffffffu, q, o);
    }
    if ((tid & 31) == 0) { red[p][wg] = s; red[p][4 + wg] = q; }
    __syncthreads();
    s = red[p][0] + red[p][1] + red[p][2] + red[p][3];
    q = red[p][4] + red[p][5] + red[p][6] + red[p][7];
    float mu = s * (1.f / HID);
    float var = q * (1.f / HID) - mu * mu;
    rep[p][j] = (v - mu) * rsqrtf(var + 1e-5f) * ln_g[j] + ln_b[j];
    __syncthreads();

    float acc = proj_b[j];
    {
        const float4* w4 = (const float4*)(projW + j * HID);
        const float4* r4 = (const float4*)&rep[p][0];
#pragma unroll
        for (int i = 0; i < 32; ++i) {
            float4 w = __ldg(&w4[i]);
            float4 r = r4[i];
            acc = fmaf(w.x, r.x, acc);
            acc = fmaf(w.y, r.y, acc);
            acc = fmaf(w.z, r.z, acc);
            acc = fmaf(w.w, r.w, acc);
        }
    }
    float tv = tanhf(acc);

    __syncthreads();   // red reuse
    float s2 = tv, q2 = tv * tv;
#pragma unroll
    for (int o = 16; o; o >>= 1) {
        s2 += __shfl_xor_sync(0xffffffffu, s2, o);
        q2 += __shfl_xor_sync(0xffffffffu, q2, o);
    }
    if ((tid & 31) == 0) { red[p][wg] = s2; red[p][4 + wg] = q2; }
    __syncthreads();
    s2 = red[p][0] + red[p][1] + red[p][2] + red[p][3];
    q2 = red[p][4] + red[p][5] + red[p][6] + red[p][7];
    float mu2 = s2 * (1.f / HID);
    float var2 = q2 * (1.f / HID) - mu2 * mu2;
    out[(b0 + p) * HID + j] = (tv - mu2) * rsqrtf(var2 + 1e-5f) * on_g[j] + on_b[j];
}

// ---------------------------------------------------------------------------
extern "C" void kernel_launch(void* const* d_in, const int* in_sizes, int n_in,
                              void* d_out, int out_size)
{
    const int*   x     = (const int*)  d_in[0];
    const float* emb   = (const float*)d_in[1];
    const float* Wih1  = (const float*)d_in[2];
    const float* bih1  = (const float*)d_in[3];
    const float* Whh1  = (const float*)d_in[4];
    const float* bhh1  = (const float*)d_in[5];
    const float* Wih2  = (const float*)d_in[6];
    const float* bih2  = (const float*)d_in[7];
    const float* Whh2  = (const float*)d_in[8];
    const float* bhh2  = (const float*)d_in[9];
    const float* ln_g  = (const float*)d_in[10];
    const float* ln_b  = (const float*)d_in[11];
    const float* projW = (const float*)d_in[12];
    const float* projb = (const float*)d_in[13];
    const float* on_g  = (const float*)d_in[14];
    const float* on_b  = (const float*)d_in[15];

    k_pre1<<<512, 128>>>(x, emb, Wih1, bih1, bhh1);
    k_scan<<<128, 256>>>(Whh1, Wih2, Whh2, bih2, bhh2,
                         ln_g, ln_b, projW, projb, on_g, on_b, (float*)d_out);
}

// round 14
// speedup vs baseline: 1.1397x; 1.1397x over previous
#include <cuda_runtime.h>

#define BB 256
#define TT 512
#define EMBD 64
#define HID 128

__device__ float g_pre1[(long)TT * BB * HID];   // [t][b][j], 64 MB

// tanh(x) = 1 - 2/(e^{2x}+1) via MUFU. |err| ~1e-7 per call.
__device__ __forceinline__ float fast_tanh(float x) {
    float xc = fminf(fmaxf(x, -20.f), 20.f);
    float e;
    asm("ex2.approx.f32 %0, %1;" : "=f"(e) : "f"(xc * 2.8853900817779268f));
    float r;
    asm("rcp.approx.f32 %0, %1;" : "=f"(r) : "f"(e + 1.f));
    return fmaf(-2.f, r, 1.f);
}

// ---------------------------------------------------------------------------
// Kernel 1: pre1[t][b][j] = dot(emb[x[b,t]], Wih1[j]) + b_ih1[j] + b_hh1[j]
// (proven R1 version, byte-identical)
// ---------------------------------------------------------------------------
__global__ __launch_bounds__(128) void k_pre1(
    const int* __restrict__ x, const float* __restrict__ emb,
    const float* __restrict__ Wih1, const float* __restrict__ bih1,
    const float* __restrict__ bhh1)
{
    __shared__ __align__(16) float shW[HID * 68];
    __shared__ __align__(16) float4 shE[8 * 16];
    __shared__ int shX[8];

    const int tid = threadIdx.x;

    for (int it = 0; it < 64; ++it) {
        int f = it * 128 + tid;
        int j = f >> 6, k = f & 63;
        shW[j * 68 + k] = Wih1[f];
    }
    __syncthreads();

    float Wr[64];
#pragma unroll
    for (int i = 0; i < 64; ++i) Wr[i] = shW[tid * 68 + i];
    const float bb = bih1[tid] + bhh1[tid];

    const int base = blockIdx.x * 256;
    const float4* __restrict__ e4 = (const float4*)emb;

    for (int it = 0; it < 32; ++it) {
        const int rid0 = base + it * 8;             // rid = t*256 + b
        if (tid < 8) {
            int rid = rid0 + tid;
            int t = rid >> 8, b = rid & 255;
            shX[tid] = x[b * TT + t];
        }
        __syncthreads();
        {
            int r = tid >> 4, f = tid & 15;
            shE[r * 16 + f] = e4[(long)shX[r] * 16 + f];
        }
        __syncthreads();

        float acc[8];
#pragma unroll
        for (int r = 0; r < 8; ++r) acc[r] = bb;
#pragma unroll
        for (int k4 = 0; k4 < 16; ++k4) {
#pragma unroll
            for (int r = 0; r < 8; ++r) {
                float4 e = shE[r * 16 + k4];
                acc[r] = fmaf(Wr[4 * k4 + 0], e.x, acc[r]);
                acc[r] = fmaf(Wr[4 * k4 + 1], e.y, acc[r]);
                acc[r] = fmaf(Wr[4 * k4 + 2], e.z, acc[r]);
                acc[r] = fmaf(Wr[4 * k4 + 3], e.w, acc[r]);
            }
        }
#pragma unroll
        for (int r = 0; r < 8; ++r)
            g_pre1[(long)(rid0 + r) * HID + tid] = acc[r];
        __syncthreads();
    }
}

// ---------------------------------------------------------------------------
// Kernel 2: fused two-layer scan, pipelined layer 2, 2 barriers/step,
// register-disciplined (two sequential FMA loops, XOR ring addressing).
// Iteration t computes h1_t AND h2_{t-1} from previous-iteration state.
// 128 CTAs x 256 threads; CTA handles rows b0, b0+1.
// Thread (j = tid&127, p = tid>>7) holds k-half rows of W_hh1/W_ih2/W_hh2.
// Fused epilogue at the end.
// ---------------------------------------------------------------------------
__global__ __launch_bounds__(256, 1) void k_scan(
    const float* __restrict__ Whh1, const float* __restrict__ Wih2,
    const float* __restrict__ Whh2, const float* __restrict__ bih2,
    const float* __restrict__ bhh2,
    const float* __restrict__ ln_g, const float* __restrict__ ln_b,
    const float* __restrict__ projW, const float* __restrict__ proj_b,
    const float* __restrict__ on_g, const float* __restrict__ on_b,
    float* __restrict__ out)
{
    __shared__ __align__(16) float h1s[2][2][HID];   // [buf][row][j]  h1_{t-1}
    __shared__ __align__(16) float h2s[2][2][HID];   // [buf][row][j]  h2_{t-2}
    __shared__ __align__(16) float pA[2][2][HID];    // Whh1 partials [half][row][j]
    __shared__ __align__(16) float pB[2][2][HID];    // Wih2+Whh2 partials
    __shared__ __align__(16) float rep[2][HID];
    __shared__ float red[2][8];

    const int tid = threadIdx.x;
    const int j = tid & 127;
    const int p = tid >> 7;            // k-half (warp-uniform)
    const int b0 = blockIdx.x * 2;

    float W1r[64], Wi2r[64], W2r[64];
    {
        const float* w1 = Whh1 + j * HID + p * 64;
        const float* wi = Wih2 + j * HID + p * 64;
        const float* w2 = Whh2 + j * HID + p * 64;
#pragma unroll
        for (int i = 0; i < 64; ++i) { W1r[i] = w1[i]; Wi2r[i] = wi[i]; W2r[i] = w2[i]; }
    }
    const float bb2 = bih2[j] + bhh2[j];

    h1s[0][p][j] = 0.f; h1s[1][p][j] = 0.f;
    h2s[0][p][j] = 0.f; h2s[1][p][j] = 0.f;
    __syncthreads();

    const float* preBase = g_pre1 + (long)(b0 + p) * HID + j;
    float pre_r = preBase[0];

    // Base pointers at buf 0, k-half p; buffer toggled via +cur*64 float4s.
    const float4* h1base = (const float4*)&h1s[0][0][p * 64];
    const float4* h2base = (const float4*)&h2s[0][0][p * 64];

    for (int t = 0; t <= TT; ++t) {
        const int cur = t & 1, nxt = cur ^ 1;
        const int off = cur * 64;                  // buf stride = 256 floats

        // ---- Loop A: Whh1 . h1_{t-1} partials (both rows) ----
        {
            const float4* u0 = h1base + off;       // row 0
            const float4* u1 = u0 + 32;            // row 1 (+128 floats)
            float a0 = 0.f, a1 = 0.f;
#pragma unroll
            for (int i = 0; i < 16; ++i) {
                float4 h0 = u0[i];
                a0 = fmaf(W1r[4 * i + 0], h0.x, a0);
                a0 = fmaf(W1r[4 * i + 1], h0.y, a0);
                a0 = fmaf(W1r[4 * i + 2], h0.z, a0);
                a0 = fmaf(W1r[4 * i + 3], h0.w, a0);
                float4 h1 = u1[i];
                a1 = fmaf(W1r[4 * i + 0], h1.x, a1);
                a1 = fmaf(W1r[4 * i + 1], h1.y, a1);
                a1 = fmaf(W1r[4 * i + 2], h1.z, a1);
                a1 = fmaf(W1r[4 * i + 3], h1.w, a1);
            }
            pA[p][0][j] = a0;
            pA[p][1][j] = a1;
        }
        asm volatile("" ::: "memory");             // keep loops from interleaving

        // ---- Loop B: Wih2 . h1_{t-1} + Whh2 . h2_{t-2} partials ----
        {
            const float4* u0 = h1base + off;
            const float4* u1 = u0 + 32;
            const float4* v0 = h2base + off;
            const float4* v1 = v0 + 32;
            float f0 = 0.f, f1 = 0.f;
#pragma unroll
            for (int i = 0; i < 16; ++i) {
                float4 h0 = u0[i];
                f0 = fmaf(Wi2r[4 * i + 0], h0.x, f0);
                f0 = fmaf(Wi2r[4 * i + 1], h0.y, f0);
                f0 = fmaf(Wi2r[4 * i + 2], h0.z, f0);
                f0 = fmaf(Wi2r[4 * i + 3], h0.w, f0);
                float4 h1 = u1[i];
                f1 = fmaf(Wi2r[4 * i + 0], h1.x, f1);
                f1 = fmaf(Wi2r[4 * i + 1], h1.y, f1);
                f1 = fmaf(Wi2r[4 * i + 2], h1.z, f1);
                f1 = fmaf(Wi2r[4 * i + 3], h1.w, f1);
                float4 g0 = v0[i];
                f0 = fmaf(W2r[4 * i + 0], g0.x, f0);
                f0 = fmaf(W2r[4 * i + 1], g0.y, f0);
                f0 = fmaf(W2r[4 * i + 2], g0.z, f0);
                f0 = fmaf(W2r[4 * i + 3], g0.w, f0);
                float4 g1 = v1[i];
                f1 = fmaf(W2r[4 * i + 0], g1.x, f1);
                f1 = fmaf(W2r[4 * i + 1], g1.y, f1);
                f1 = fmaf(W2r[4 * i + 2], g1.z, f1);
                f1 = fmaf(W2r[4 * i + 3], g1.w, f1);
            }
            pB[p][0][j] = f0;
            pB[p][1][j] = f1;
        }
        __syncthreads();                           // BAR 1: partials ready

        // ---- Combine: thread (j,p) finishes row p for h1_t and h2_{t-1} ----
        if (t < TT) {
            float v = pre_r + pA[0][p][j] + pA[1][p][j];
            h1s[nxt][p][j] = fast_tanh(v);
            if (t + 1 < TT) pre_r = preBase[(long)(t + 1) * BB * HID];
        }
        h2s[nxt][p][j] = (t == 0) ? 0.f
                         : fast_tanh(bb2 + pB[0][p][j] + pB[1][p][j]);
        __syncthreads();                           // BAR 2: new state ready
    }

    // h2_{TT-1} is in h2s[1] (written at t=TT, nxt = (TT&1)^1 = 1).
    // ---- Fused epilogue: LN -> proj -> tanh -> LN for row p ----
    const int wg = (tid >> 5) & 3;
    float v = h2s[1][p][j];

    float s = v, q = v * v;
#pragma unroll
    for (int o = 16; o; o >>= 1) {
        s += __shfl_xor_sync(0xffffffffu, s, o);
        q += __shfl_xor_sync(0xffffffffu, q, o);
    }
    if ((tid & 31) == 0) { red[p][wg] = s; red[p][4 + wg] = q; }
    __syncthreads();
    s = red[p][0] + red[p][1] + red[p][2] + red[p][3];
    q = red[p][4] + red[p][5] + red[p][6] + red[p][7];
    float mu = s * (1.f / HID);
    float var = q * (1.f / HID) - mu * mu;
    rep[p][j] = (v - mu) * rsqrtf(var + 1e-5f) * ln_g[j] + ln_b[j];
    __syncthreads();

    float acc = proj_b[j];
    {
        const float4* w4 = (const float4*)(projW + j * HID);
        const float4* r4 = (const float4*)&rep[p][0];
#pragma unroll
        for (int i = 0; i < 32; ++i) {
            float4 w = __ldg(&w4[i]);
            float4 r = r4[i];
            acc = fmaf(w.x, r.x, acc);
            acc = fmaf(w.y, r.y, acc);
            acc = fmaf(w.z, r.z, acc);
            acc = fmaf(w.w, r.w, acc);
        }
    }
    float tv = tanhf(acc);

    __syncthreads();   // red reuse
    float s2 = tv, q2 = tv * tv;
#pragma unroll
    for (int o = 16; o; o >>= 1) {
        s2 += __shfl_xor_sync(0xffffffffu, s2, o);
        q2 += __shfl_xor_sync(0xffffffffu, q2, o);
    }
    if ((tid & 31) == 0) { red[p][wg] = s2; red[p][4 + wg] = q2; }
    __syncthreads();
    s2 = red[p][0] + red[p][1] + red[p][2] + red[p][3];
    q2 = red[p][4] + red[p][5] + red[p][6] + red[p][7];
    float mu2 = s2 * (1.f / HID);
    float var2 = q2 * (1.f / HID) - mu2 * mu2;
    out[(b0 + p) * HID + j] = (tv - mu2) * rsqrtf(var2 + 1e-5f) * on_g[j] + on_b[j];
}

// ---------------------------------------------------------------------------
extern "C" void kernel_launch(void* const* d_in, const int* in_sizes, int n_in,
                              void* d_out, int out_size)
{
    const int*   x     = (const int*)  d_in[0];
    const float* emb   = (const float*)d_in[1];
    const float* Wih1  = (const float*)d_in[2];
    const float* bih1  = (const float*)d_in[3];
    const float* Whh1  = (const float*)d_in[4];
    const float* bhh1  = (const float*)d_in[5];
    const float* Wih2  = (const float*)d_in[6];
    const float* bih2  = (const float*)d_in[7];
    const float* Whh2  = (const float*)d_in[8];
    const float* bhh2  = (const float*)d_in[9];
    const float* ln_g  = (const float*)d_in[10];
    const float* ln_b  = (const float*)d_in[11];
    const float* projW = (const float*)d_in[12];
    const float* projb = (const float*)d_in[13];
    const float* on_g  = (const float*)d_in[14];
    const float* on_b  = (const float*)d_in[15];

    k_pre1<<<512, 128>>>(x, emb, Wih1, bih1, bhh1);
    k_scan<<<128, 256>>>(Whh1, Wih2, Whh2, bih2, bhh2,
                         ln_g, ln_b, projW, projb, on_g, on_b, (float*)d_out);
}

// round 15
// speedup vs baseline: 1.3253x; 1.1628x over previous
#include <cuda_runtime.h>

#define BB 256
#define TT 512
#define EMBD 64
#define HID 128

__device__ float g_pre1[(long)TT * BB * HID];   // [t][b][j], 64 MB

// ---------------------------------------------------------------------------
// Kernel 1: pre1[t][b][j] = dot(emb[x[b,t]], Wih1[j]) + b_ih1[j] + b_hh1[j]
// (proven R1 version, byte-identical)
// ---------------------------------------------------------------------------
__global__ __launch_bounds__(128) void k_pre1(
    const int* __restrict__ x, const float* __restrict__ emb,
    const float* __restrict__ Wih1, const float* __restrict__ bih1,
    const float* __restrict__ bhh1)
{
    __shared__ __align__(16) float shW[HID * 68];
    __shared__ __align__(16) float4 shE[8 * 16];
    __shared__ int shX[8];

    const int tid = threadIdx.x;

    for (int it = 0; it < 64; ++it) {
        int f = it * 128 + tid;
        int j = f >> 6, k = f & 63;
        shW[j * 68 + k] = Wih1[f];
    }
    __syncthreads();

    float Wr[64];
#pragma unroll
    for (int i = 0; i < 64; ++i) Wr[i] = shW[tid * 68 + i];
    const float bb = bih1[tid] + bhh1[tid];

    const int base = blockIdx.x * 256;
    const float4* __restrict__ e4 = (const float4*)emb;

    for (int it = 0; it < 32; ++it) {
        const int rid0 = base + it * 8;             // rid = t*256 + b
        if (tid < 8) {
            int rid = rid0 + tid;
            int t = rid >> 8, b = rid & 255;
            shX[tid] = x[b * TT + t];
        }
        __syncthreads();
        {
            int r = tid >> 4, f = tid & 15;
            shE[r * 16 + f] = e4[(long)shX[r] * 16 + f];
        }
        __syncthreads();

        float acc[8];
#pragma unroll
        for (int r = 0; r < 8; ++r) acc[r] = bb;
#pragma unroll
        for (int k4 = 0; k4 < 16; ++k4) {
#pragma unroll
            for (int r = 0; r < 8; ++r) {
                float4 e = shE[r * 16 + k4];
                acc[r] = fmaf(Wr[4 * k4 + 0], e.x, acc[r]);
                acc[r] = fmaf(Wr[4 * k4 + 1], e.y, acc[r]);
                acc[r] = fmaf(Wr[4 * k4 + 2], e.z, acc[r]);
                acc[r] = fmaf(Wr[4 * k4 + 3], e.w, acc[r]);
            }
        }
#pragma unroll
        for (int r = 0; r < 8; ++r)
            g_pre1[(long)(rid0 + r) * HID + tid] = acc[r];
        __syncthreads();
    }
}

// ---------------------------------------------------------------------------
// Kernel 2: R1's fused two-layer scan with:
//   * double-buffered h2 + split pA/pB  => 3 barriers/step instead of 4
//   * fused epilogue (LN -> proj -> tanh -> LN), k_epi deleted
// 128 blocks x 256 threads; block handles rows b0, b0+1.
// Thread (j = tid&127, p = tid>>7) holds k-half rows of W_hh1/W_ih2/W_hh2.
// Phases (identical math to R1):
//   A: partials of W_hh1*h1_old (both rows) -> pA        [BAR1]
//   B: h1_new = tanhf(pre + sum(pA)) for row p (in-place)[BAR2]
//   C: partials of W_ih2*h1_new + W_hh2*h2_cur -> pB     [BAR3]
//   D: h2_nxt = tanhf(bb2 + sum(pB)) for row p  (no barrier; next BAR1 covers)
// ---------------------------------------------------------------------------
__global__ __launch_bounds__(256, 1) void k_scan(
    const float* __restrict__ Whh1, const float* __restrict__ Wih2,
    const float* __restrict__ Whh2, const float* __restrict__ bih2,
    const float* __restrict__ bhh2,
    const float* __restrict__ ln_g, const float* __restrict__ ln_b,
    const float* __restrict__ projW, const float* __restrict__ proj_b,
    const float* __restrict__ on_g, const float* __restrict__ on_b,
    float* __restrict__ out)
{
    __shared__ __align__(16) float sh_h1[2][HID];     // [row][j], in-place
    __shared__ __align__(16) float h2s[2][2][HID];    // [buf][row][j]
    __shared__ __align__(16) float pA[2][2][HID];     // [half][row][j]
    __shared__ __align__(16) float pB[2][2][HID];     // [half][row][j]
    __shared__ __align__(16) float rep[2][HID];
    __shared__ float red[2][8];

    const int tid = threadIdx.x;
    const int j = tid & 127;
    const int p = tid >> 7;            // k-half (uniform per warp)
    const int b0 = blockIdx.x * 2;

    float W1r[64], Wi2r[64], W2r[64];
    {
        const float* w1 = Whh1 + j * HID + p * 64;
        const float* wi = Wih2 + j * HID + p * 64;
        const float* w2 = Whh2 + j * HID + p * 64;
#pragma unroll
        for (int i = 0; i < 64; ++i) { W1r[i] = w1[i]; Wi2r[i] = wi[i]; W2r[i] = w2[i]; }
    }
    const float bb2 = bih2[j] + bhh2[j];

    sh_h1[p][j] = 0.f;
    h2s[0][p][j] = 0.f;
    h2s[1][p][j] = 0.f;
    __syncthreads();

    const float* preBase = g_pre1 + (long)(b0 + p) * HID + j;
    float pre_r = preBase[0];

    const float4* h10p = (const float4*)&sh_h1[0][p * 64];
    const float4* h11p = (const float4*)&sh_h1[1][p * 64];
    const float4* h2base = (const float4*)&h2s[0][0][p * 64];   // buf stride 64 f4

    for (int t = 0; t < TT; ++t) {
        const int cur = t & 1, nxt = cur ^ 1;

        // ---- Phase A: partials of W_hh1 * h1_old for both rows ----
        float a0 = 0.f, a1 = 0.f;
#pragma unroll
        for (int i = 0; i < 16; ++i) {
            float4 h0 = h10p[i];
            a0 = fmaf(W1r[4 * i + 0], h0.x, a0);
            a0 = fmaf(W1r[4 * i + 1], h0.y, a0);
            a0 = fmaf(W1r[4 * i + 2], h0.z, a0);
            a0 = fmaf(W1r[4 * i + 3], h0.w, a0);
            float4 h1 = h11p[i];
            a1 = fmaf(W1r[4 * i + 0], h1.x, a1);
            a1 = fmaf(W1r[4 * i + 1], h1.y, a1);
            a1 = fmaf(W1r[4 * i + 2], h1.z, a1);
            a1 = fmaf(W1r[4 * i + 3], h1.w, a1);
        }
        pA[p][0][j] = a0;
        pA[p][1][j] = a1;
        __syncthreads();                              // BAR1

        // ---- Phase B: h1_new = tanh(pre + sum) for row p ----
        {
            float v = pre_r + pA[0][p][j] + pA[1][p][j];
            sh_h1[p][j] = tanhf(v);
        }
        if (t + 1 < TT) pre_r = preBase[(long)(t + 1) * BB * HID];
        __syncthreads();                              // BAR2

        // ---- Phase C: partials of W_ih2*h1_new + W_hh2*h2_cur ----
        {
            const float4* g0 = h2base + cur * 64;     // buf cur, row 0
            const float4* g1 = g0 + 32;               // row 1
            float c0 = 0.f, c1 = 0.f, d0 = 0.f, d1 = 0.f;
#pragma unroll
            for (int i = 0; i < 16; ++i) {
                float4 h0 = h10p[i];
                c0 = fmaf(Wi2r[4 * i + 0], h0.x, c0);
                c0 = fmaf(Wi2r[4 * i + 1], h0.y, c0);
                c0 = fmaf(Wi2r[4 * i + 2], h0.z, c0);
                c0 = fmaf(Wi2r[4 * i + 3], h0.w, c0);
                float4 h1 = h11p[i];
                c1 = fmaf(Wi2r[4 * i + 0], h1.x, c1);
                c1 = fmaf(Wi2r[4 * i + 1], h1.y, c1);
                c1 = fmaf(Wi2r[4 * i + 2], h1.z, c1);
                c1 = fmaf(Wi2r[4 * i + 3], h1.w, c1);
                float4 u0 = g0[i];
                d0 = fmaf(W2r[4 * i + 0], u0.x, d0);
                d0 = fmaf(W2r[4 * i + 1], u0.y, d0);
                d0 = fmaf(W2r[4 * i + 2], u0.z, d0);
                d0 = fmaf(W2r[4 * i + 3], u0.w, d0);
                float4 u1 = g1[i];
                d1 = fmaf(W2r[4 * i + 0], u1.x, d1);
                d1 = fmaf(W2r[4 * i + 1], u1.y, d1);
                d1 = fmaf(W2r[4 * i + 2], u1.z, d1);
                d1 = fmaf(W2r[4 * i + 3], u1.w, d1);
            }
            pB[p][0][j] = c0 + d0;
            pB[p][1][j] = c1 + d1;
        }
        __syncthreads();                              // BAR3

        // ---- Phase D: h2_nxt = tanh(bb2 + sum) for row p (no barrier) ----
        {
            float v2 = bb2 + pB[0][p][j] + pB[1][p][j];
            h2s[nxt][p][j] = tanhf(v2);
        }
        // No barrier: next iteration's phase A touches only pA / sh_h1 reads,
        // and BAR1(t+1) orders this write before phase C(t+1) reads it.
    }

    // Final h2: last write at t=511 went to buf nxt = 0; each thread reads its
    // own element (own write -> no sync needed before the reduction below).
    const int wg = (tid >> 5) & 3;
    float v = h2s[0][p][j];

    // ---- LN 1 over row p ----
    float s = v, q = v * v;
#pragma unroll
    for (int o = 16; o; o >>= 1) {
        s += __shfl_xor_sync(0xffffffffu, s, o);
        q += __shfl_xor_sync(0xffffffffu, q, o);
    }
    if ((tid & 31) == 0) { red[p][wg] = s; red[p][4 + wg] = q; }
    __syncthreads();
    s = red[p][0] + red[p][1] + red[p][2] + red[p][3];
    q = red[p][4] + red[p][5] + red[p][6] + red[p][7];
    float mu = s * (1.f / HID);
    float var = q * (1.f / HID) - mu * mu;
    rep[p][j] = (v - mu) * rsqrtf(var + 1e-5f) * ln_g[j] + ln_b[j];
    __syncthreads();

    // ---- proj + tanh ----
    float acc = proj_b[j];
    {
        const float4* w4 = (const float4*)(projW + j * HID);
        const float4* r4 = (const float4*)&rep[p][0];
#pragma unroll
        for (int i = 0; i < 32; ++i) {
            float4 w = __ldg(&w4[i]);
            float4 r = r4[i];
            acc = fmaf(w.x, r.x, acc);
            acc = fmaf(w.y, r.y, acc);
            acc = fmaf(w.z, r.z, acc);
            acc = fmaf(w.w, r.w, acc);
        }
    }
    float tv = tanhf(acc);

    // ---- LN 2 ----
    __syncthreads();   // red reuse
    float s2 = tv, q2 = tv * tv;
#pragma unroll
    for (int o = 16; o; o >>= 1) {
        s2 += __shfl_xor_sync(0xffffffffu, s2, o);
        q2 += __shfl_xor_sync(0xffffffffu, q2, o);
    }
    if ((tid & 31) == 0) { red[p][wg] = s2; red[p][4 + wg] = q2; }
    __syncthreads();
    s2 = red[p][0] + red[p][1] + red[p][2] + red[p][3];
    q2 = red[p][4] + red[p][5] + red[p][6] + red[p][7];
    float mu2 = s2 * (1.f / HID);
    float var2 = q2 * (1.f / HID) - mu2 * mu2;
    out[(b0 + p) * HID + j] = (tv - mu2) * rsqrtf(var2 + 1e-5f) * on_g[j] + on_b[j];
}

// ---------------------------------------------------------------------------
extern "C" void kernel_launch(void* const* d_in, const int* in_sizes, int n_in,
                              void* d_out, int out_size)
{
    const int*   x     = (const int*)  d_in[0];
    const float* emb   = (const float*)d_in[1];
    const float* Wih1  = (const float*)d_in[2];
    const float* bih1  = (const float*)d_in[3];
    const float* Whh1  = (const float*)d_in[4];
    const float* bhh1  = (const float*)d_in[5];
    const float* Wih2  = (const float*)d_in[6];
    const float* bih2  = (const float*)d_in[7];
    const float* Whh2  = (const float*)d_in[8];
    const float* bhh2  = (const float*)d_in[9];
    const float* ln_g  = (const float*)d_in[10];
    const float* ln_b  = (const float*)d_in[11];
    const float* projW = (const float*)d_in[12];
    const float* projb = (const float*)d_in[13];
    const float* on_g  = (const float*)d_in[14];
    const float* on_b  = (const float*)d_in[15];

    k_pre1<<<512, 128>>>(x, emb, Wih1, bih1, bhh1);
    k_scan<<<128, 256>>>(Whh1, Wih2, Whh2, bih2, bhh2,
                         ln_g, ln_b, projW, projb, on_g, on_b, (float*)d_out);
}